// round 14
// baseline (speedup 1.0000x reference)
#include <cuda_runtime.h>
#include <math.h>

// ---------------- problem constants ----------------
#define B_   64
#define C_   256
#define HW_  4096            // 64*64
#define NBLK 7               // CTAs per batch -> grid 448 <= 456 (3 CTAs/SM x 152)
#define PLANES 128
#define HIDDEN 16
#define K_   8
#define ATT_CH 4
#define EPS_ 1e-5f

// ---------------- device scratch (zero-init at load; last CTA re-zeros) ----------------
__device__ float    g_sumc[B_ * C_];
__device__ float    g_num [B_ * C_];
__device__ float    g_D   [B_];
__device__ float    g_summ[B_];
__device__ unsigned g_cnt [B_];

__global__ __launch_bounds__(256, 3) void fused(
        const float* __restrict__ x,
        const float* __restrict__ w_mask, const float* __restrict__ b_mask,
        const float* __restrict__ w_cm1, const float* __restrict__ b_cm1,
        const float* __restrict__ ln_w,  const float* __restrict__ ln_b,
        const float* __restrict__ w_cm2, const float* __restrict__ b_cm2,
        const float* __restrict__ w_net1, const float* __restrict__ w_net2,
        const float* __restrict__ w_fc,
        const float* __restrict__ bn_w,  const float* __restrict__ bn_b,
        const float* __restrict__ bn_mean, const float* __restrict__ bn_var,
        const float* __restrict__ w_kfc,
        float* __restrict__ out) {
    // smem: double-buffered partials AL[2][8][64], AM[2][8][64]; finalize aliases [0..1081)
    __shared__ __align__(16) float sm[2064];
    __shared__ int s_last;
    float* AL = sm;           // slot s at sm + s*512
    float* AM = sm + 1024;    // slot s at sm + 1024 + s*512

    const int t    = threadIdx.x;    // 0..255
    const int lane = t & 31;
    const int w    = t >> 5;
    const int b    = blockIdx.x / NBLK;
    const int j    = blockIdx.x - b * NBLK;   // 0..6 within batch

    // rounds of 2 tiles (64 positions): 1 CTA x 10 + 6 CTAs x 9 = 64 rounds = 128 tiles
    const int rounds = (j == 0) ? 10 : 9;
    const int tile0  = (j == 0) ? 0 : 20 + (j - 1) * 18;

    const int cg = t >> 3;           // channel group 0..31 (channels cg*8+i)
    const int q  = t & 7;            // position quad 0..7

    // hoisted mask weights for this thread's 8 channels
    float4 wv0 = *reinterpret_cast<const float4*>(w_mask + cg * 8);
    float4 wv1 = *reinterpret_cast<const float4*>(w_mask + cg * 8 + 4);
    const float wreg[8] = {wv0.x, wv0.y, wv0.z, wv0.w, wv1.x, wv1.y, wv1.z, wv1.w};
    const float bm = b_mask[0];

    // thread-fixed row pointer (lanes 0-7 cover one full 128B line -> nL=4)
    const float4* xr = reinterpret_cast<const float4*>(x) + (size_t)b * C_ * (HW_ / 4)
                     + (size_t)(cg * 8) * (HW_ / 4) + q;

    // accumulators
    float sv[8], sve[8];
    #pragma unroll
    for (int i = 0; i < 8; ++i) { sv[i] = 0.f; sve[i] = 0.f; }
    float run_e = 0.f, run_m = 0.f;     // warp 0 lanes

    #pragma unroll 1
    for (int r = 0; r < rounds; ++r) {
        const size_t offA = (size_t)(tile0 + 2 * r) * 8;
        const size_t offB = offA + 8;
        const int slot = r & 1;

        // ---- phase2 tile A: burst-load, consume, free ----
        float4 lpA = make_float4(0.f, 0.f, 0.f, 0.f);
        float4 mpA = make_float4(-1e30f, -1e30f, -1e30f, -1e30f);
        {
            float4 d[8];
            #pragma unroll
            for (int i = 0; i < 8; ++i) d[i] = __ldg(xr + (size_t)i * (HW_ / 4) + offA);
            #pragma unroll
            for (int i = 0; i < 8; ++i) {
                const float wc = wreg[i];
                lpA.x = fmaf(d[i].x, wc, lpA.x); lpA.y = fmaf(d[i].y, wc, lpA.y);
                lpA.z = fmaf(d[i].z, wc, lpA.z); lpA.w = fmaf(d[i].w, wc, lpA.w);
                mpA.x = fmaxf(mpA.x, d[i].x);    mpA.y = fmaxf(mpA.y, d[i].y);
                mpA.z = fmaxf(mpA.z, d[i].z);    mpA.w = fmaxf(mpA.w, d[i].w);
                sv[i] += (d[i].x + d[i].y) + (d[i].z + d[i].w);
            }
        }
        // ---- phase2 tile B ----
        float4 lpB = make_float4(0.f, 0.f, 0.f, 0.f);
        float4 mpB = make_float4(-1e30f, -1e30f, -1e30f, -1e30f);
        {
            float4 d[8];
            #pragma unroll
            for (int i = 0; i < 8; ++i) d[i] = __ldg(xr + (size_t)i * (HW_ / 4) + offB);
            #pragma unroll
            for (int i = 0; i < 8; ++i) {
                const float wc = wreg[i];
                lpB.x = fmaf(d[i].x, wc, lpB.x); lpB.y = fmaf(d[i].y, wc, lpB.y);
                lpB.z = fmaf(d[i].z, wc, lpB.z); lpB.w = fmaf(d[i].w, wc, lpB.w);
                mpB.x = fmaxf(mpB.x, d[i].x);    mpB.y = fmaxf(mpB.y, d[i].y);
                mpB.z = fmaxf(mpB.z, d[i].z);    mpB.w = fmaxf(mpB.w, d[i].w);
                sv[i] += (d[i].x + d[i].y) + (d[i].z + d[i].w);
            }
        }

        // intra-warp reduce over the 4 channel-groups (lanes stride 8, same q)
        #pragma unroll
        for (int off = 8; off <= 16; off <<= 1) {
            lpA.x += __shfl_down_sync(0xffffffffu, lpA.x, off);
            lpA.y += __shfl_down_sync(0xffffffffu, lpA.y, off);
            lpA.z += __shfl_down_sync(0xffffffffu, lpA.z, off);
            lpA.w += __shfl_down_sync(0xffffffffu, lpA.w, off);
            lpB.x += __shfl_down_sync(0xffffffffu, lpB.x, off);
            lpB.y += __shfl_down_sync(0xffffffffu, lpB.y, off);
            lpB.z += __shfl_down_sync(0xffffffffu, lpB.z, off);
            lpB.w += __shfl_down_sync(0xffffffffu, lpB.w, off);
            mpA.x = fmaxf(mpA.x, __shfl_down_sync(0xffffffffu, mpA.x, off));
            mpA.y = fmaxf(mpA.y, __shfl_down_sync(0xffffffffu, mpA.y, off));
            mpA.z = fmaxf(mpA.z, __shfl_down_sync(0xffffffffu, mpA.z, off));
            mpA.w = fmaxf(mpA.w, __shfl_down_sync(0xffffffffu, mpA.w, off));
            mpB.x = fmaxf(mpB.x, __shfl_down_sync(0xffffffffu, mpB.x, off));
            mpB.y = fmaxf(mpB.y, __shfl_down_sync(0xffffffffu, mpB.y, off));
            mpB.z = fmaxf(mpB.z, __shfl_down_sync(0xffffffffu, mpB.z, off));
            mpB.w = fmaxf(mpB.w, __shfl_down_sync(0xffffffffu, mpB.w, off));
        }
        if (lane < 8) {
            *reinterpret_cast<float4*>(AL + slot * 512 + w * 64 + lane * 4)      = lpA;
            *reinterpret_cast<float4*>(AL + slot * 512 + w * 64 + 32 + lane * 4) = lpB;
            *reinterpret_cast<float4*>(AM + slot * 512 + w * 64 + lane * 4)      = mpA;
            *reinterpret_cast<float4*>(AM + slot * 512 + w * 64 + 32 + lane * 4) = mpB;
        }
        __syncthreads();     // the ONLY barrier per round (slots double-buffered)

        // ---- combine (every warp redundantly; lane covers positions lane, lane+32)
        float la = bm, lb = bm;
        #pragma unroll
        for (int p = 0; p < 8; ++p) {
            la += AL[slot * 512 + p * 64 + lane];
            lb += AL[slot * 512 + p * 64 + 32 + lane];
        }
        const float ea = __expf(la);     // unnormalized softmax weights (logits O(3))
        const float eb = __expf(lb);
        if (w == 0) {
            run_e += ea + eb;
            float ma = -1e30f, mb2 = -1e30f;
            #pragma unroll
            for (int p = 0; p < 8; ++p) {
                ma  = fmaxf(ma,  AM[slot * 512 + p * 64 + lane]);
                mb2 = fmaxf(mb2, AM[slot * 512 + p * 64 + 32 + lane]);
            }
            run_m += ma + mb2;
        }

        // ---- phase3: re-read from L1 (hot) and weighted-accumulate ----
        const float eA0 = __shfl_sync(0xffffffffu, ea, q * 4 + 0);
        const float eA1 = __shfl_sync(0xffffffffu, ea, q * 4 + 1);
        const float eA2 = __shfl_sync(0xffffffffu, ea, q * 4 + 2);
        const float eA3 = __shfl_sync(0xffffffffu, ea, q * 4 + 3);
        const float eB0 = __shfl_sync(0xffffffffu, eb, q * 4 + 0);
        const float eB1 = __shfl_sync(0xffffffffu, eb, q * 4 + 1);
        const float eB2 = __shfl_sync(0xffffffffu, eb, q * 4 + 2);
        const float eB3 = __shfl_sync(0xffffffffu, eb, q * 4 + 3);
        {
            float4 d[8];
            #pragma unroll
            for (int i = 0; i < 8; ++i) d[i] = __ldg(xr + (size_t)i * (HW_ / 4) + offA);
            #pragma unroll
            for (int i = 0; i < 8; ++i) {
                float a = fmaf(d[i].x, eA0, sve[i]);
                a = fmaf(d[i].y, eA1, a);
                a = fmaf(d[i].z, eA2, a);
                sve[i] = fmaf(d[i].w, eA3, a);
            }
        }
        {
            float4 d[8];
            #pragma unroll
            for (int i = 0; i < 8; ++i) d[i] = __ldg(xr + (size_t)i * (HW_ / 4) + offB);
            #pragma unroll
            for (int i = 0; i < 8; ++i) {
                float a = fmaf(d[i].x, eB0, sve[i]);
                a = fmaf(d[i].y, eB1, a);
                a = fmaf(d[i].z, eB2, a);
                sve[i] = fmaf(d[i].w, eB3, a);
            }
        }
    }

    // ---- reduce sv/sve over the 8 q-lanes of each channel group ----
    #pragma unroll
    for (int off = 4; off > 0; off >>= 1) {
        #pragma unroll
        for (int i = 0; i < 8; ++i) {
            sv[i]  += __shfl_down_sync(0xffffffffu, sv[i],  off, 8);
            sve[i] += __shfl_down_sync(0xffffffffu, sve[i], off, 8);
        }
    }
    if (q == 0) {
        #pragma unroll
        for (int i = 0; i < 8; ++i) {
            atomicAdd(&g_sumc[b * C_ + cg * 8 + i], sv[i]);
            atomicAdd(&g_num [b * C_ + cg * 8 + i], sve[i]);
        }
    }
    if (w == 0) {
        #pragma unroll
        for (int off = 16; off > 0; off >>= 1) {
            run_e += __shfl_down_sync(0xffffffffu, run_e, off);
            run_m += __shfl_down_sync(0xffffffffu, run_m, off);
        }
        if (lane == 0) { atomicAdd(&g_D[b], run_e); atomicAdd(&g_summ[b], run_m); }
    }
    __threadfence();
    __syncthreads();
    if (t == 0) {
        unsigned old = atomicAdd(&g_cnt[b], 1u);
        s_last = (old == NBLK - 1);
    }
    __syncthreads();
    if (!s_last) return;

    // ================= finalize (last CTA of this batch) =================
    float* ctx   = sm;            // 256  (aliases partial slots — loop fully done)
    float* bcv   = sm + 256;      // 256
    float* tvs   = sm + 512;      // 128
    float* tg    = sm + 640;      // 128
    float* sout  = sm + 768;      // 256
    float* red_s = sm + 1024;     // 4
    float* red_q = sm + 1028;     // 4
    float* red_a = sm + 1032;     // 8
    float* hid   = sm + 1040;     // 16
    float* o8    = sm + 1056;     // 8
    float* kar   = sm + 1064;     // 4
    float* fvv   = sm + 1072;     // 8
    float* shm   = sm + 1080;     // 1

    const int wp = w;

    const float Dv    = __ldcg(&g_D[b]);
    const float summv = __ldcg(&g_summ[b]);
    const float numv  = __ldcg(&g_num [b * C_ + t]);
    const float sumcv = __ldcg(&g_sumc[b * C_ + t]);

    ctx[t] = numv  * (1.f / Dv);
    bcv[t] = sumcv * (1.f / (float)HW_);
    {
        float s = sumcv * (1.f / (float)HW_);
        #pragma unroll
        for (int off = 16; off > 0; off >>= 1) s += __shfl_down_sync(0xffffffffu, s, off);
        if (lane == 0) red_a[wp] = s;
    }
    __syncthreads();   // all threads have loaded g_* before any re-zero (race fix)

    // re-zero scratch for next graph replay
    g_num [b * C_ + t] = 0.f;
    g_sumc[b * C_ + t] = 0.f;
    if (t == 0) { g_D[b] = 0.f; g_summ[b] = 0.f; g_cnt[b] = 0u; shm[0] = summv * (1.f / (float)HW_); }
    __syncthreads();

    const float aval = (red_a[0] + red_a[1] + red_a[2] + red_a[3] +
                        red_a[4] + red_a[5] + red_a[6] + red_a[7]) * (1.f / (float)C_);
    const float mv = shm[0];

    // conv1 (128x256): warp wp -> planes wp*16..+15
    {
        const float4* ctx4 = reinterpret_cast<const float4*>(ctx);
        const float4 c0 = ctx4[lane];
        const float4 c1 = ctx4[lane + 32];
        #pragma unroll 4
        for (int i = 0; i < 16; ++i) {
            int p = wp * 16 + i;
            const float4* w4 = reinterpret_cast<const float4*>(w_cm1 + p * C_);
            float4 a0 = w4[lane];
            float4 a1 = w4[lane + 32];
            float pr = a0.x * c0.x + a0.y * c0.y + a0.z * c0.z + a0.w * c0.w
                     + a1.x * c1.x + a1.y * c1.y + a1.z * c1.z + a1.w * c1.w;
            #pragma unroll
            for (int off = 16; off > 0; off >>= 1)
                pr += __shfl_down_sync(0xffffffffu, pr, off);
            if (lane == 0) tvs[p] = pr + b_cm1[p];
        }
    }
    __syncthreads();

    // LayerNorm(128) + exact GELU
    {
        float tvv = (t < PLANES) ? tvs[t] : 0.f;
        float s1 = tvv, s2 = tvv * tvv;
        #pragma unroll
        for (int off = 16; off > 0; off >>= 1) {
            s1 += __shfl_down_sync(0xffffffffu, s1, off);
            s2 += __shfl_down_sync(0xffffffffu, s2, off);
        }
        if (t < PLANES && lane == 0) { red_s[wp] = s1; red_q[wp] = s2; }
        __syncthreads();
        if (t < PLANES) {
            float S  = red_s[0] + red_s[1] + red_s[2] + red_s[3];
            float SQ = red_q[0] + red_q[1] + red_q[2] + red_q[3];
            float mu  = S * (1.f / PLANES);
            float var = SQ * (1.f / PLANES) - mu * mu;
            float tn = (tvv - mu) * rsqrtf(var + EPS_) * ln_w[t] + ln_b[t];
            tg[t] = 0.5f * tn * (1.f + erff(tn * 0.70710678118654752f));
        }
    }
    __syncthreads();

    // conv2 (256x128): warp wp -> channels wp*32..+31
    {
        const float4* tg4 = reinterpret_cast<const float4*>(tg);
        const float4 g0 = tg4[lane];
        #pragma unroll 4
        for (int i = 0; i < 32; ++i) {
            int ch = wp * 32 + i;
            const float4* w4 = reinterpret_cast<const float4*>(w_cm2 + ch * PLANES);
            float4 a0 = w4[lane];
            float pr = a0.x * g0.x + a0.y * g0.y + a0.z * g0.z + a0.w * g0.w;
            #pragma unroll
            for (int off = 16; off > 0; off >>= 1)
                pr += __shfl_down_sync(0xffffffffu, pr, off);
            if (lane == 0)
                sout[ch] = bcv[ch] + pr + b_cm2[ch] + ((ch & 1) ? mv : aval);
        }
    }
    __syncthreads();

    // net1 (16x256): warp wp -> hidden wp*2, wp*2+1
    {
        const float4* so4 = reinterpret_cast<const float4*>(sout);
        const float4 s0 = so4[lane];
        const float4 s1v = so4[lane + 32];
        #pragma unroll
        for (int jj = 0; jj < 2; ++jj) {
            int hh = wp * 2 + jj;
            const float4* w4 = reinterpret_cast<const float4*>(w_net1 + hh * C_);
            float4 a0 = w4[lane];
            float4 a1 = w4[lane + 32];
            float pr = a0.x * s0.x + a0.y * s0.y + a0.z * s0.z + a0.w * s0.w
                     + a1.x * s1v.x + a1.y * s1v.y + a1.z * s1v.z + a1.w * s1v.w;
            #pragma unroll
            for (int off = 16; off > 0; off >>= 1)
                pr += __shfl_down_sync(0xffffffffu, pr, off);
            if (lane == 0) hid[hh] = fmaxf(pr, 0.f);
        }
    }
    __syncthreads();

    if (t < K_) {
        float o = 0.f;
        #pragma unroll
        for (int q2 = 0; q2 < HIDDEN; ++q2) o = fmaf(hid[q2], w_net2[t * HIDDEN + q2], o);
        o8[t] = o;
    }
    __syncthreads();
    if (t < ATT_CH) {
        float ka = 0.f;
        #pragma unroll
        for (int k = 0; k < K_; ++k) ka = fmaf(o8[k], w_fc[t * K_ + k], ka);
        ka = (ka - bn_mean[t]) * rsqrtf(bn_var[t] + EPS_) * bn_w[t] + bn_b[t];
        kar[t] = fmaxf(ka, 0.f);
    }
    __syncthreads();
    if (t < K_) {
        float kk = 0.f;
        #pragma unroll
        for (int q2 = 0; q2 < ATT_CH; ++q2) kk = fmaf(kar[q2], w_kfc[t * ATT_CH + q2], kk);
        float ker = 1.f / (1.f + __expf(-kk));
        fvv[t] = o8[t] * ker * (1.f / 30.f);
    }
    __syncthreads();
    if (t == 0) {
        float mx = -1e30f;
        #pragma unroll
        for (int k = 0; k < K_; ++k) mx = fmaxf(mx, fvv[k]);
        float e[K_], s = 0.f;
        #pragma unroll
        for (int k = 0; k < K_; ++k) { e[k] = __expf(fvv[k] - mx); s += e[k]; }
        float inv = 1.f / s;
        #pragma unroll
        for (int k = 0; k < K_; ++k) out[b * K_ + k] = e[k] * inv;
    }
}

// ---------------- launch ----------------
extern "C" void kernel_launch(void* const* d_in, const int* in_sizes, int n_in,
                              void* d_out, int out_size) {
    const float* x      = (const float*)d_in[0];
    const float* w_mask = (const float*)d_in[1];
    const float* b_mask = (const float*)d_in[2];
    const float* w_cm1  = (const float*)d_in[3];
    const float* b_cm1  = (const float*)d_in[4];
    const float* ln_w   = (const float*)d_in[5];
    const float* ln_b   = (const float*)d_in[6];
    const float* w_cm2  = (const float*)d_in[7];
    const float* b_cm2  = (const float*)d_in[8];
    const float* w_net1 = (const float*)d_in[9];
    const float* w_net2 = (const float*)d_in[10];
    const float* w_fc   = (const float*)d_in[11];
    const float* bn_w   = (const float*)d_in[12];
    const float* bn_b   = (const float*)d_in[13];
    const float* bn_mean= (const float*)d_in[14];
    const float* bn_var = (const float*)d_in[15];
    const float* w_kfc  = (const float*)d_in[16];
    float* out = (float*)d_out;

    fused<<<B_ * NBLK, 256>>>(x, w_mask, b_mask,
                          w_cm1, b_cm1, ln_w, ln_b, w_cm2, b_cm2,
                          w_net1, w_net2, w_fc, bn_w, bn_b, bn_mean, bn_var,
                          w_kfc, out);
}

// round 15
// speedup vs baseline: 1.5913x; 1.5913x over previous
#include <cuda_runtime.h>
#include <math.h>

// ---------------- problem constants ----------------
#define B_   64
#define C_   256
#define HW_  4096            // 64*64
#define NBLK 4               // CTAs per batch -> grid 256 (2 CTAs/SM x 152 = 304)
#define PLANES 128
#define HIDDEN 16
#define K_   8
#define ATT_CH 4
#define EPS_ 1e-5f

// ---------------- device scratch (zero-init at load; last CTA re-zeros) ----------------
__device__ float    g_sumc[B_ * C_];
__device__ float    g_num [B_ * C_];
__device__ float    g_D   [B_];
__device__ float    g_summ[B_];
__device__ unsigned g_cnt [B_];

__global__ __launch_bounds__(256, 2) void fused(
        const float* __restrict__ x,
        const float* __restrict__ w_mask, const float* __restrict__ b_mask,
        const float* __restrict__ w_cm1, const float* __restrict__ b_cm1,
        const float* __restrict__ ln_w,  const float* __restrict__ ln_b,
        const float* __restrict__ w_cm2, const float* __restrict__ b_cm2,
        const float* __restrict__ w_net1, const float* __restrict__ w_net2,
        const float* __restrict__ w_fc,
        const float* __restrict__ bn_w,  const float* __restrict__ bn_b,
        const float* __restrict__ bn_mean, const float* __restrict__ bn_var,
        const float* __restrict__ w_kfc,
        float* __restrict__ out) {
    // smem: double-buffered partials AL[2][8][64], AM[2][8][64]; finalize aliases [0..1081)
    __shared__ __align__(16) float sm[2064];
    __shared__ int s_last;
    float* AL = sm;           // slot s at sm + s*512
    float* AM = sm + 1024;    // slot s at sm + 1024 + s*512

    const int t    = threadIdx.x;    // 0..255
    const int lane = t & 31;
    const int w    = t >> 5;
    const int b    = blockIdx.x >> 2;
    const int j    = blockIdx.x & 3;          // 0..3 within batch

    const int tile0 = j * 32;        // 32 tiles (32 positions each) per CTA; 16 rounds

    const int cg = t >> 3;           // channel group 0..31 (channels cg*8+i)
    const int q  = t & 7;            // position quad 0..7

    // hoisted mask weights for this thread's 8 channels
    float4 wv0 = *reinterpret_cast<const float4*>(w_mask + cg * 8);
    float4 wv1 = *reinterpret_cast<const float4*>(w_mask + cg * 8 + 4);
    const float wreg[8] = {wv0.x, wv0.y, wv0.z, wv0.w, wv1.x, wv1.y, wv1.z, wv1.w};
    const float bm = b_mask[0];

    // thread-fixed row pointer (lanes 0-7 cover one full 128B line -> nL=4)
    const float4* xr = reinterpret_cast<const float4*>(x) + (size_t)b * C_ * (HW_ / 4)
                     + (size_t)(cg * 8) * (HW_ / 4) + q;

    // per-thread accumulators (channel cg*8+i over this thread's positions)
    float sv[8], sve[8];
    #pragma unroll
    for (int i = 0; i < 8; ++i) { sv[i] = 0.f; sve[i] = 0.f; }
    float run_e = 0.f, run_m = 0.f;     // warp 0 lanes

    #pragma unroll 1
    for (int r = 0; r < 16; ++r) {
        const size_t off0 = (size_t)(tile0 + 2 * r) * 8;   // tile A (32 pos)
        const size_t off1 = off0 + 8;                      // tile B (next 32 pos)
        const int slot = r & 1;

        // ---- 16 independent coalesced streaming LDG.128 (2KB/warp burst) ----
        float4 d0[8], d1[8];
        #pragma unroll
        for (int i = 0; i < 8; ++i) {
            d0[i] = __ldcs(xr + (size_t)i * (HW_ / 4) + off0);
            d1[i] = __ldcs(xr + (size_t)i * (HW_ / 4) + off1);
        }

        // ---- phase2: logit / max / channel-sum partials for both tiles ----
        float4 lp0 = make_float4(0.f, 0.f, 0.f, 0.f);
        float4 lp1 = make_float4(0.f, 0.f, 0.f, 0.f);
        float4 mp0 = make_float4(-1e30f, -1e30f, -1e30f, -1e30f);
        float4 mp1 = make_float4(-1e30f, -1e30f, -1e30f, -1e30f);
        #pragma unroll
        for (int i = 0; i < 8; ++i) {
            const float wc = wreg[i];
            lp0.x = fmaf(d0[i].x, wc, lp0.x); lp0.y = fmaf(d0[i].y, wc, lp0.y);
            lp0.z = fmaf(d0[i].z, wc, lp0.z); lp0.w = fmaf(d0[i].w, wc, lp0.w);
            lp1.x = fmaf(d1[i].x, wc, lp1.x); lp1.y = fmaf(d1[i].y, wc, lp1.y);
            lp1.z = fmaf(d1[i].z, wc, lp1.z); lp1.w = fmaf(d1[i].w, wc, lp1.w);
            mp0.x = fmaxf(mp0.x, d0[i].x);    mp0.y = fmaxf(mp0.y, d0[i].y);
            mp0.z = fmaxf(mp0.z, d0[i].z);    mp0.w = fmaxf(mp0.w, d0[i].w);
            mp1.x = fmaxf(mp1.x, d1[i].x);    mp1.y = fmaxf(mp1.y, d1[i].y);
            mp1.z = fmaxf(mp1.z, d1[i].z);    mp1.w = fmaxf(mp1.w, d1[i].w);
            sv[i] += (d0[i].x + d0[i].y) + (d0[i].z + d0[i].w)
                   + (d1[i].x + d1[i].y) + (d1[i].z + d1[i].w);
        }
        // intra-warp reduce over the 4 channel-groups (lanes stride 8, same q)
        #pragma unroll
        for (int off = 8; off <= 16; off <<= 1) {
            lp0.x += __shfl_down_sync(0xffffffffu, lp0.x, off);
            lp0.y += __shfl_down_sync(0xffffffffu, lp0.y, off);
            lp0.z += __shfl_down_sync(0xffffffffu, lp0.z, off);
            lp0.w += __shfl_down_sync(0xffffffffu, lp0.w, off);
            lp1.x += __shfl_down_sync(0xffffffffu, lp1.x, off);
            lp1.y += __shfl_down_sync(0xffffffffu, lp1.y, off);
            lp1.z += __shfl_down_sync(0xffffffffu, lp1.z, off);
            lp1.w += __shfl_down_sync(0xffffffffu, lp1.w, off);
            mp0.x = fmaxf(mp0.x, __shfl_down_sync(0xffffffffu, mp0.x, off));
            mp0.y = fmaxf(mp0.y, __shfl_down_sync(0xffffffffu, mp0.y, off));
            mp0.z = fmaxf(mp0.z, __shfl_down_sync(0xffffffffu, mp0.z, off));
            mp0.w = fmaxf(mp0.w, __shfl_down_sync(0xffffffffu, mp0.w, off));
            mp1.x = fmaxf(mp1.x, __shfl_down_sync(0xffffffffu, mp1.x, off));
            mp1.y = fmaxf(mp1.y, __shfl_down_sync(0xffffffffu, mp1.y, off));
            mp1.z = fmaxf(mp1.z, __shfl_down_sync(0xffffffffu, mp1.z, off));
            mp1.w = fmaxf(mp1.w, __shfl_down_sync(0xffffffffu, mp1.w, off));
        }
        // store to this round's slot; WAR vs combine(r-2) separated by barrier(r-1)
        if (lane < 8) {
            *reinterpret_cast<float4*>(AL + slot * 512 + w * 64 + lane * 4)      = lp0;
            *reinterpret_cast<float4*>(AL + slot * 512 + w * 64 + 32 + lane * 4) = lp1;
            *reinterpret_cast<float4*>(AM + slot * 512 + w * 64 + lane * 4)      = mp0;
            *reinterpret_cast<float4*>(AM + slot * 512 + w * 64 + 32 + lane * 4) = mp1;
        }
        __syncthreads();     // the ONLY barrier per round

        // ---- combine (every warp redundantly; lane covers positions lane & lane+32)
        float la = bm, lb = bm;
        #pragma unroll
        for (int p = 0; p < 8; ++p) {
            la += AL[slot * 512 + p * 64 + lane];
            lb += AL[slot * 512 + p * 64 + 32 + lane];
        }
        const float ea = __expf(la);     // unnormalized softmax weights (logits O(3))
        const float eb = __expf(lb);
        if (w == 0) {
            run_e += ea + eb;
            float ma = -1e30f, mb2 = -1e30f;
            #pragma unroll
            for (int p = 0; p < 8; ++p) {
                ma  = fmaxf(ma,  AM[slot * 512 + p * 64 + lane]);
                mb2 = fmaxf(mb2, AM[slot * 512 + p * 64 + 32 + lane]);
            }
            run_m += ma + mb2;
        }

        // ---- phase3: weighted accumulate from the SAME registers ----
        const float e0 = __shfl_sync(0xffffffffu, ea, q * 4 + 0);
        const float e1 = __shfl_sync(0xffffffffu, ea, q * 4 + 1);
        const float e2 = __shfl_sync(0xffffffffu, ea, q * 4 + 2);
        const float e3 = __shfl_sync(0xffffffffu, ea, q * 4 + 3);
        const float e4 = __shfl_sync(0xffffffffu, eb, q * 4 + 0);
        const float e5 = __shfl_sync(0xffffffffu, eb, q * 4 + 1);
        const float e6 = __shfl_sync(0xffffffffu, eb, q * 4 + 2);
        const float e7 = __shfl_sync(0xffffffffu, eb, q * 4 + 3);
        #pragma unroll
        for (int i = 0; i < 8; ++i) {
            float a = fmaf(d0[i].x, e0, sve[i]);
            a = fmaf(d0[i].y, e1, a);
            a = fmaf(d0[i].z, e2, a);
            a = fmaf(d0[i].w, e3, a);
            a = fmaf(d1[i].x, e4, a);
            a = fmaf(d1[i].y, e5, a);
            a = fmaf(d1[i].z, e6, a);
            sve[i] = fmaf(d1[i].w, e7, a);
        }
    }

    // ---- reduce sv/sve over the 8 q-lanes of each channel group ----
    #pragma unroll
    for (int off = 4; off > 0; off >>= 1) {
        #pragma unroll
        for (int i = 0; i < 8; ++i) {
            sv[i]  += __shfl_down_sync(0xffffffffu, sv[i],  off, 8);
            sve[i] += __shfl_down_sync(0xffffffffu, sve[i], off, 8);
        }
    }
    if (q == 0) {
        #pragma unroll
        for (int i = 0; i < 8; ++i) {
            atomicAdd(&g_sumc[b * C_ + cg * 8 + i], sv[i]);
            atomicAdd(&g_num [b * C_ + cg * 8 + i], sve[i]);
        }
    }
    if (w == 0) {
        #pragma unroll
        for (int off = 16; off > 0; off >>= 1) {
            run_e += __shfl_down_sync(0xffffffffu, run_e, off);
            run_m += __shfl_down_sync(0xffffffffu, run_m, off);
        }
        if (lane == 0) { atomicAdd(&g_D[b], run_e); atomicAdd(&g_summ[b], run_m); }
    }
    __threadfence();
    __syncthreads();
    if (t == 0) {
        unsigned old = atomicAdd(&g_cnt[b], 1u);
        s_last = (old == NBLK - 1);
    }
    __syncthreads();
    if (!s_last) return;

    // ================= finalize (last CTA of this batch) =================
    float* ctx   = sm;            // 256  (aliases partial slots — loop fully done)
    float* bcv   = sm + 256;      // 256
    float* tvs   = sm + 512;      // 128
    float* tg    = sm + 640;      // 128
    float* sout  = sm + 768;      // 256
    float* red_s = sm + 1024;     // 4
    float* red_q = sm + 1028;     // 4
    float* red_a = sm + 1032;     // 8
    float* hid   = sm + 1040;     // 16
    float* o8    = sm + 1056;     // 8
    float* kar   = sm + 1064;     // 4
    float* fvv   = sm + 1072;     // 8
    float* shm   = sm + 1080;     // 1

    const int wp = w;

    const float Dv    = __ldcg(&g_D[b]);
    const float summv = __ldcg(&g_summ[b]);
    const float numv  = __ldcg(&g_num [b * C_ + t]);
    const float sumcv = __ldcg(&g_sumc[b * C_ + t]);

    ctx[t] = numv  * (1.f / Dv);
    bcv[t] = sumcv * (1.f / (float)HW_);
    {
        float s = sumcv * (1.f / (float)HW_);
        #pragma unroll
        for (int off = 16; off > 0; off >>= 1) s += __shfl_down_sync(0xffffffffu, s, off);
        if (lane == 0) red_a[wp] = s;
    }
    __syncthreads();   // all threads have loaded g_* before any re-zero (race fix)

    // re-zero scratch for next graph replay
    g_num [b * C_ + t] = 0.f;
    g_sumc[b * C_ + t] = 0.f;
    if (t == 0) { g_D[b] = 0.f; g_summ[b] = 0.f; g_cnt[b] = 0u; shm[0] = summv * (1.f / (float)HW_); }
    __syncthreads();

    const float aval = (red_a[0] + red_a[1] + red_a[2] + red_a[3] +
                        red_a[4] + red_a[5] + red_a[6] + red_a[7]) * (1.f / (float)C_);
    const float mv = shm[0];

    // conv1 (128x256): warp wp -> planes wp*16..+15
    {
        const float4* ctx4 = reinterpret_cast<const float4*>(ctx);
        const float4 c0 = ctx4[lane];
        const float4 c1 = ctx4[lane + 32];
        #pragma unroll 4
        for (int i = 0; i < 16; ++i) {
            int p = wp * 16 + i;
            const float4* w4 = reinterpret_cast<const float4*>(w_cm1 + p * C_);
            float4 a0 = w4[lane];
            float4 a1 = w4[lane + 32];
            float pr = a0.x * c0.x + a0.y * c0.y + a0.z * c0.z + a0.w * c0.w
                     + a1.x * c1.x + a1.y * c1.y + a1.z * c1.z + a1.w * c1.w;
            #pragma unroll
            for (int off = 16; off > 0; off >>= 1)
                pr += __shfl_down_sync(0xffffffffu, pr, off);
            if (lane == 0) tvs[p] = pr + b_cm1[p];
        }
    }
    __syncthreads();

    // LayerNorm(128) + exact GELU
    {
        float tvv = (t < PLANES) ? tvs[t] : 0.f;
        float s1 = tvv, s2 = tvv * tvv;
        #pragma unroll
        for (int off = 16; off > 0; off >>= 1) {
            s1 += __shfl_down_sync(0xffffffffu, s1, off);
            s2 += __shfl_down_sync(0xffffffffu, s2, off);
        }
        if (t < PLANES && lane == 0) { red_s[wp] = s1; red_q[wp] = s2; }
        __syncthreads();
        if (t < PLANES) {
            float S  = red_s[0] + red_s[1] + red_s[2] + red_s[3];
            float SQ = red_q[0] + red_q[1] + red_q[2] + red_q[3];
            float mu  = S * (1.f / PLANES);
            float var = SQ * (1.f / PLANES) - mu * mu;
            float tn = (tvv - mu) * rsqrtf(var + EPS_) * ln_w[t] + ln_b[t];
            tg[t] = 0.5f * tn * (1.f + erff(tn * 0.70710678118654752f));
        }
    }
    __syncthreads();

    // conv2 (256x128): warp wp -> channels wp*32..+31
    {
        const float4* tg4 = reinterpret_cast<const float4*>(tg);
        const float4 g0 = tg4[lane];
        #pragma unroll 4
        for (int i = 0; i < 32; ++i) {
            int ch = wp * 32 + i;
            const float4* w4 = reinterpret_cast<const float4*>(w_cm2 + ch * PLANES);
            float4 a0 = w4[lane];
            float pr = a0.x * g0.x + a0.y * g0.y + a0.z * g0.z + a0.w * g0.w;
            #pragma unroll
            for (int off = 16; off > 0; off >>= 1)
                pr += __shfl_down_sync(0xffffffffu, pr, off);
            if (lane == 0)
                sout[ch] = bcv[ch] + pr + b_cm2[ch] + ((ch & 1) ? mv : aval);
        }
    }
    __syncthreads();

    // net1 (16x256): warp wp -> hidden wp*2, wp*2+1
    {
        const float4* so4 = reinterpret_cast<const float4*>(sout);
        const float4 s0 = so4[lane];
        const float4 s1v = so4[lane + 32];
        #pragma unroll
        for (int jj = 0; jj < 2; ++jj) {
            int hh = wp * 2 + jj;
            const float4* w4 = reinterpret_cast<const float4*>(w_net1 + hh * C_);
            float4 a0 = w4[lane];
            float4 a1 = w4[lane + 32];
            float pr = a0.x * s0.x + a0.y * s0.y + a0.z * s0.z + a0.w * s0.w
                     + a1.x * s1v.x + a1.y * s1v.y + a1.z * s1v.z + a1.w * s1v.w;
            #pragma unroll
            for (int off = 16; off > 0; off >>= 1)
                pr += __shfl_down_sync(0xffffffffu, pr, off);
            if (lane == 0) hid[hh] = fmaxf(pr, 0.f);
        }
    }
    __syncthreads();

    if (t < K_) {
        float o = 0.f;
        #pragma unroll
        for (int q2 = 0; q2 < HIDDEN; ++q2) o = fmaf(hid[q2], w_net2[t * HIDDEN + q2], o);
        o8[t] = o;
    }
    __syncthreads();
    if (t < ATT_CH) {
        float ka = 0.f;
        #pragma unroll
        for (int k = 0; k < K_; ++k) ka = fmaf(o8[k], w_fc[t * K_ + k], ka);
        ka = (ka - bn_mean[t]) * rsqrtf(bn_var[t] + EPS_) * bn_w[t] + bn_b[t];
        kar[t] = fmaxf(ka, 0.f);
    }
    __syncthreads();
    if (t < K_) {
        float kk = 0.f;
        #pragma unroll
        for (int q2 = 0; q2 < ATT_CH; ++q2) kk = fmaf(kar[q2], w_kfc[t * ATT_CH + q2], kk);
        float ker = 1.f / (1.f + __expf(-kk));
        fvv[t] = o8[t] * ker * (1.f / 30.f);
    }
    __syncthreads();
    if (t == 0) {
        float mx = -1e30f;
        #pragma unroll
        for (int k = 0; k < K_; ++k) mx = fmaxf(mx, fvv[k]);
        float e[K_], s = 0.f;
        #pragma unroll
        for (int k = 0; k < K_; ++k) { e[k] = __expf(fvv[k] - mx); s += e[k]; }
        float inv = 1.f / s;
        #pragma unroll
        for (int k = 0; k < K_; ++k) out[b * K_ + k] = e[k] * inv;
    }
}

// ---------------- launch ----------------
extern "C" void kernel_launch(void* const* d_in, const int* in_sizes, int n_in,
                              void* d_out, int out_size) {
    const float* x      = (const float*)d_in[0];
    const float* w_mask = (const float*)d_in[1];
    const float* b_mask = (const float*)d_in[2];
    const float* w_cm1  = (const float*)d_in[3];
    const float* b_cm1  = (const float*)d_in[4];
    const float* ln_w   = (const float*)d_in[5];
    const float* ln_b   = (const float*)d_in[6];
    const float* w_cm2  = (const float*)d_in[7];
    const float* b_cm2  = (const float*)d_in[8];
    const float* w_net1 = (const float*)d_in[9];
    const float* w_net2 = (const float*)d_in[10];
    const float* w_fc   = (const float*)d_in[11];
    const float* bn_w   = (const float*)d_in[12];
    const float* bn_b   = (const float*)d_in[13];
    const float* bn_mean= (const float*)d_in[14];
    const float* bn_var = (const float*)d_in[15];
    const float* w_kfc  = (const float*)d_in[16];
    float* out = (float*)d_out;

    fused<<<B_ * NBLK, 256>>>(x, w_mask, b_mask,
                          w_cm1, b_cm1, ln_w, ln_b, w_cm2, b_cm2,
                          w_net1, w_net2, w_fc, bn_w, bn_b, bn_mean, bn_var,
                          w_kfc, out);
}

// round 16
// speedup vs baseline: 1.6506x; 1.0373x over previous
#include <cuda_runtime.h>
#include <math.h>

// ---------------- problem constants ----------------
#define B_   64
#define C_   256
#define HW_  4096            // 64*64
#define GRID 304             // 2 CTAs/SM x 152 SMs -> exactly one full wave
#define TPB_TILES 128        // 32-pos tiles per batch
#define PLANES 128
#define HIDDEN 16
#define K_   8
#define ATT_CH 4
#define EPS_ 1e-5f

// ---------------- device scratch (zero-init at load; finalize re-zeros) ----------------
__device__ float    g_sumc[B_ * C_];
__device__ float    g_num [B_ * C_];
__device__ float    g_D   [B_];
__device__ float    g_summ[B_];
__device__ unsigned g_cnt [B_];     // tiles accumulated per batch

// ---------------- finalize: runs in whichever CTA completes a batch ----------------
__device__ __forceinline__ void finalize_batch(
        int b, float* sm, int t, int lane, int wp,
        const float* __restrict__ w_cm1, const float* __restrict__ b_cm1,
        const float* __restrict__ ln_w,  const float* __restrict__ ln_b,
        const float* __restrict__ w_cm2, const float* __restrict__ b_cm2,
        const float* __restrict__ w_net1, const float* __restrict__ w_net2,
        const float* __restrict__ w_fc,
        const float* __restrict__ bn_w,  const float* __restrict__ bn_b,
        const float* __restrict__ bn_mean, const float* __restrict__ bn_var,
        const float* __restrict__ w_kfc,
        float* __restrict__ out) {
    float* ctx   = sm;            // 256
    float* bcv   = sm + 256;      // 256
    float* tvs   = sm + 512;      // 128
    float* tg    = sm + 640;      // 128
    float* sout  = sm + 768;      // 256
    float* red_s = sm + 1024;     // 4
    float* red_q = sm + 1028;     // 4
    float* red_a = sm + 1032;     // 8
    float* hid   = sm + 1040;     // 16
    float* o8    = sm + 1056;     // 8
    float* kar   = sm + 1064;     // 4
    float* fvv   = sm + 1072;     // 8
    float* shm   = sm + 1080;     // 1

    const float Dv    = __ldcg(&g_D[b]);
    const float summv = __ldcg(&g_summ[b]);
    const float numv  = __ldcg(&g_num [b * C_ + t]);
    const float sumcv = __ldcg(&g_sumc[b * C_ + t]);

    ctx[t] = numv  * (1.f / Dv);
    bcv[t] = sumcv * (1.f / (float)HW_);
    {
        float s = sumcv * (1.f / (float)HW_);
        #pragma unroll
        for (int off = 16; off > 0; off >>= 1) s += __shfl_down_sync(0xffffffffu, s, off);
        if (lane == 0) red_a[wp] = s;
    }
    __syncthreads();   // RACE FIX: all threads loaded g_* before any re-zero

    // re-zero scratch for next graph replay
    g_num [b * C_ + t] = 0.f;
    g_sumc[b * C_ + t] = 0.f;
    if (t == 0) { g_D[b] = 0.f; g_summ[b] = 0.f; g_cnt[b] = 0u; shm[0] = summv * (1.f / (float)HW_); }
    __syncthreads();

    const float aval = (red_a[0] + red_a[1] + red_a[2] + red_a[3] +
                        red_a[4] + red_a[5] + red_a[6] + red_a[7]) * (1.f / (float)C_);
    const float mv = shm[0];

    // conv1 (128x256): warp wp -> planes wp*16..+15
    {
        const float4* ctx4 = reinterpret_cast<const float4*>(ctx);
        const float4 c0 = ctx4[lane];
        const float4 c1 = ctx4[lane + 32];
        #pragma unroll 4
        for (int i = 0; i < 16; ++i) {
            int p = wp * 16 + i;
            const float4* w4 = reinterpret_cast<const float4*>(w_cm1 + p * C_);
            float4 a0 = w4[lane];
            float4 a1 = w4[lane + 32];
            float pr = a0.x * c0.x + a0.y * c0.y + a0.z * c0.z + a0.w * c0.w
                     + a1.x * c1.x + a1.y * c1.y + a1.z * c1.z + a1.w * c1.w;
            #pragma unroll
            for (int off = 16; off > 0; off >>= 1)
                pr += __shfl_down_sync(0xffffffffu, pr, off);
            if (lane == 0) tvs[p] = pr + b_cm1[p];
        }
    }
    __syncthreads();

    // LayerNorm(128) + exact GELU
    {
        float tvv = (t < PLANES) ? tvs[t] : 0.f;
        float s1 = tvv, s2 = tvv * tvv;
        #pragma unroll
        for (int off = 16; off > 0; off >>= 1) {
            s1 += __shfl_down_sync(0xffffffffu, s1, off);
            s2 += __shfl_down_sync(0xffffffffu, s2, off);
        }
        if (t < PLANES && lane == 0) { red_s[wp] = s1; red_q[wp] = s2; }
        __syncthreads();
        if (t < PLANES) {
            float S  = red_s[0] + red_s[1] + red_s[2] + red_s[3];
            float SQ = red_q[0] + red_q[1] + red_q[2] + red_q[3];
            float mu  = S * (1.f / PLANES);
            float var = SQ * (1.f / PLANES) - mu * mu;
            float tn = (tvv - mu) * rsqrtf(var + EPS_) * ln_w[t] + ln_b[t];
            tg[t] = 0.5f * tn * (1.f + erff(tn * 0.70710678118654752f));
        }
    }
    __syncthreads();

    // conv2 (256x128): warp wp -> channels wp*32..+31
    {
        const float4* tg4 = reinterpret_cast<const float4*>(tg);
        const float4 g0 = tg4[lane];
        #pragma unroll 4
        for (int i = 0; i < 32; ++i) {
            int ch = wp * 32 + i;
            const float4* w4 = reinterpret_cast<const float4*>(w_cm2 + ch * PLANES);
            float4 a0 = w4[lane];
            float pr = a0.x * g0.x + a0.y * g0.y + a0.z * g0.z + a0.w * g0.w;
            #pragma unroll
            for (int off = 16; off > 0; off >>= 1)
                pr += __shfl_down_sync(0xffffffffu, pr, off);
            if (lane == 0)
                sout[ch] = bcv[ch] + pr + b_cm2[ch] + ((ch & 1) ? mv : aval);
        }
    }
    __syncthreads();

    // net1 (16x256): warp wp -> hidden wp*2, wp*2+1
    {
        const float4* so4 = reinterpret_cast<const float4*>(sout);
        const float4 s0 = so4[lane];
        const float4 s1v = so4[lane + 32];
        #pragma unroll
        for (int jj = 0; jj < 2; ++jj) {
            int hh = wp * 2 + jj;
            const float4* w4 = reinterpret_cast<const float4*>(w_net1 + hh * C_);
            float4 a0 = w4[lane];
            float4 a1 = w4[lane + 32];
            float pr = a0.x * s0.x + a0.y * s0.y + a0.z * s0.z + a0.w * s0.w
                     + a1.x * s1v.x + a1.y * s1v.y + a1.z * s1v.z + a1.w * s1v.w;
            #pragma unroll
            for (int off = 16; off > 0; off >>= 1)
                pr += __shfl_down_sync(0xffffffffu, pr, off);
            if (lane == 0) hid[hh] = fmaxf(pr, 0.f);
        }
    }
    __syncthreads();

    if (t < K_) {
        float o = 0.f;
        #pragma unroll
        for (int q2 = 0; q2 < HIDDEN; ++q2) o = fmaf(hid[q2], w_net2[t * HIDDEN + q2], o);
        o8[t] = o;
    }
    __syncthreads();
    if (t < ATT_CH) {
        float ka = 0.f;
        #pragma unroll
        for (int k = 0; k < K_; ++k) ka = fmaf(o8[k], w_fc[t * K_ + k], ka);
        ka = (ka - bn_mean[t]) * rsqrtf(bn_var[t] + EPS_) * bn_w[t] + bn_b[t];
        kar[t] = fmaxf(ka, 0.f);
    }
    __syncthreads();
    if (t < K_) {
        float kk = 0.f;
        #pragma unroll
        for (int q2 = 0; q2 < ATT_CH; ++q2) kk = fmaf(kar[q2], w_kfc[t * ATT_CH + q2], kk);
        float ker = 1.f / (1.f + __expf(-kk));
        fvv[t] = o8[t] * ker * (1.f / 30.f);
    }
    __syncthreads();
    if (t == 0) {
        float mx = -1e30f;
        #pragma unroll
        for (int k = 0; k < K_; ++k) mx = fmaxf(mx, fvv[k]);
        float e[K_], s = 0.f;
        #pragma unroll
        for (int k = 0; k < K_; ++k) { e[k] = __expf(fvv[k] - mx); s += e[k]; }
        float inv = 1.f / s;
        #pragma unroll
        for (int k = 0; k < K_; ++k) out[b * K_ + k] = e[k] * inv;
    }
    __syncthreads();   // smem handed back to the streaming loop
}

// ---------------- persistent fused kernel ----------------
__global__ __launch_bounds__(256, 2) void fused(
        const float* __restrict__ x,
        const float* __restrict__ w_mask, const float* __restrict__ b_mask,
        const float* __restrict__ w_cm1, const float* __restrict__ b_cm1,
        const float* __restrict__ ln_w,  const float* __restrict__ ln_b,
        const float* __restrict__ w_cm2, const float* __restrict__ b_cm2,
        const float* __restrict__ w_net1, const float* __restrict__ w_net2,
        const float* __restrict__ w_fc,
        const float* __restrict__ bn_w,  const float* __restrict__ bn_b,
        const float* __restrict__ bn_mean, const float* __restrict__ bn_var,
        const float* __restrict__ w_kfc,
        float* __restrict__ out) {
    // smem: double-buffered partials AL[2][8][64], AM[2][8][64]; finalize aliases [0..1081)
    __shared__ __align__(16) float sm[2064];
    __shared__ int s_last;
    float* AL = sm;           // slot s at sm + s*512
    float* AM = sm + 1024;    // slot s at sm + 1024 + s*512

    const int t    = threadIdx.x;    // 0..255
    const int lane = t & 31;
    const int w    = t >> 5;
    const int r    = blockIdx.x;

    // even tile ranges: 144 CTAs x 28 + 160 CTAs x 26 = 8192 tiles
    const int nrounds = (r < 144) ? 14 : 13;                  // rounds of 2 tiles
    const int tstart  = (r < 144) ? r * 28 : 4032 + (r - 144) * 26;

    const int cg = t >> 3;           // channel group 0..31 (channels cg*8+i)
    const int q  = t & 7;            // position quad 0..7

    // hoisted mask weights for this thread's 8 channels
    float4 wv0 = *reinterpret_cast<const float4*>(w_mask + cg * 8);
    float4 wv1 = *reinterpret_cast<const float4*>(w_mask + cg * 8 + 4);
    const float wreg[8] = {wv0.x, wv0.y, wv0.z, wv0.w, wv1.x, wv1.y, wv1.z, wv1.w};
    const float bm = b_mask[0];

    const float4* x4 = reinterpret_cast<const float4*>(x);
    const size_t croff = (size_t)(cg * 8) * (HW_ / 4) + q;   // channel-row + quad offset

    // per-thread accumulators (reset at each flush)
    float sv[8], sve[8];
    #pragma unroll
    for (int i = 0; i < 8; ++i) { sv[i] = 0.f; sve[i] = 0.f; }
    float run_e = 0.f, run_m = 0.f;     // warp 0 lanes
    int acc_tiles = 0;

    #pragma unroll 1
    for (int rr = 0; rr < nrounds; ++rr) {
        const int T = tstart + 2 * rr;       // global tile index (even)
        const int b = T >> 7;
        const size_t base = (size_t)b * C_ * (HW_ / 4) + croff
                          + (size_t)(T & 127) * 8;
        const int slot = rr & 1;

        // ---- 16 independent coalesced streaming LDG.128 (2KB/warp burst) ----
        float4 d0[8], d1[8];
        #pragma unroll
        for (int i = 0; i < 8; ++i) {
            d0[i] = __ldcs(x4 + base + (size_t)i * (HW_ / 4));
            d1[i] = __ldcs(x4 + base + (size_t)i * (HW_ / 4) + 8);
        }

        // ---- phase2: logit / max / channel-sum partials for both tiles ----
        float4 lp0 = make_float4(0.f, 0.f, 0.f, 0.f);
        float4 lp1 = make_float4(0.f, 0.f, 0.f, 0.f);
        float4 mp0 = make_float4(-1e30f, -1e30f, -1e30f, -1e30f);
        float4 mp1 = make_float4(-1e30f, -1e30f, -1e30f, -1e30f);
        #pragma unroll
        for (int i = 0; i < 8; ++i) {
            const float wc = wreg[i];
            lp0.x = fmaf(d0[i].x, wc, lp0.x); lp0.y = fmaf(d0[i].y, wc, lp0.y);
            lp0.z = fmaf(d0[i].z, wc, lp0.z); lp0.w = fmaf(d0[i].w, wc, lp0.w);
            lp1.x = fmaf(d1[i].x, wc, lp1.x); lp1.y = fmaf(d1[i].y, wc, lp1.y);
            lp1.z = fmaf(d1[i].z, wc, lp1.z); lp1.w = fmaf(d1[i].w, wc, lp1.w);
            mp0.x = fmaxf(mp0.x, d0[i].x);    mp0.y = fmaxf(mp0.y, d0[i].y);
            mp0.z = fmaxf(mp0.z, d0[i].z);    mp0.w = fmaxf(mp0.w, d0[i].w);
            mp1.x = fmaxf(mp1.x, d1[i].x);    mp1.y = fmaxf(mp1.y, d1[i].y);
            mp1.z = fmaxf(mp1.z, d1[i].z);    mp1.w = fmaxf(mp1.w, d1[i].w);
            sv[i] += (d0[i].x + d0[i].y) + (d0[i].z + d0[i].w)
                   + (d1[i].x + d1[i].y) + (d1[i].z + d1[i].w);
        }
        // intra-warp reduce over the 4 channel-groups (lanes stride 8, same q)
        #pragma unroll
        for (int off = 8; off <= 16; off <<= 1) {
            lp0.x += __shfl_down_sync(0xffffffffu, lp0.x, off);
            lp0.y += __shfl_down_sync(0xffffffffu, lp0.y, off);
            lp0.z += __shfl_down_sync(0xffffffffu, lp0.z, off);
            lp0.w += __shfl_down_sync(0xffffffffu, lp0.w, off);
            lp1.x += __shfl_down_sync(0xffffffffu, lp1.x, off);
            lp1.y += __shfl_down_sync(0xffffffffu, lp1.y, off);
            lp1.z += __shfl_down_sync(0xffffffffu, lp1.z, off);
            lp1.w += __shfl_down_sync(0xffffffffu, lp1.w, off);
            mp0.x = fmaxf(mp0.x, __shfl_down_sync(0xffffffffu, mp0.x, off));
            mp0.y = fmaxf(mp0.y, __shfl_down_sync(0xffffffffu, mp0.y, off));
            mp0.z = fmaxf(mp0.z, __shfl_down_sync(0xffffffffu, mp0.z, off));
            mp0.w = fmaxf(mp0.w, __shfl_down_sync(0xffffffffu, mp0.w, off));
            mp1.x = fmaxf(mp1.x, __shfl_down_sync(0xffffffffu, mp1.x, off));
            mp1.y = fmaxf(mp1.y, __shfl_down_sync(0xffffffffu, mp1.y, off));
            mp1.z = fmaxf(mp1.z, __shfl_down_sync(0xffffffffu, mp1.z, off));
            mp1.w = fmaxf(mp1.w, __shfl_down_sync(0xffffffffu, mp1.w, off));
        }
        // store to this round's slot; WAR vs combine(rr-2) separated by barrier(rr-1)
        if (lane < 8) {
            *reinterpret_cast<float4*>(AL + slot * 512 + w * 64 + lane * 4)      = lp0;
            *reinterpret_cast<float4*>(AL + slot * 512 + w * 64 + 32 + lane * 4) = lp1;
            *reinterpret_cast<float4*>(AM + slot * 512 + w * 64 + lane * 4)      = mp0;
            *reinterpret_cast<float4*>(AM + slot * 512 + w * 64 + 32 + lane * 4) = mp1;
        }
        __syncthreads();     // the ONLY barrier per round

        // ---- combine (every warp redundantly; lane covers positions lane & lane+32)
        float la = bm, lb = bm;
        #pragma unroll
        for (int p = 0; p < 8; ++p) {
            la += AL[slot * 512 + p * 64 + lane];
            lb += AL[slot * 512 + p * 64 + 32 + lane];
        }
        const float ea = __expf(la);     // unnormalized softmax weights (logits O(3))
        const float eb = __expf(lb);
        if (w == 0) {
            run_e += ea + eb;
            float ma = -1e30f, mb2 = -1e30f;
            #pragma unroll
            for (int p = 0; p < 8; ++p) {
                ma  = fmaxf(ma,  AM[slot * 512 + p * 64 + lane]);
                mb2 = fmaxf(mb2, AM[slot * 512 + p * 64 + 32 + lane]);
            }
            run_m += ma + mb2;
        }

        // ---- phase3: weighted accumulate from the SAME registers ----
        const float e0 = __shfl_sync(0xffffffffu, ea, q * 4 + 0);
        const float e1 = __shfl_sync(0xffffffffu, ea, q * 4 + 1);
        const float e2 = __shfl_sync(0xffffffffu, ea, q * 4 + 2);
        const float e3 = __shfl_sync(0xffffffffu, ea, q * 4 + 3);
        const float e4 = __shfl_sync(0xffffffffu, eb, q * 4 + 0);
        const float e5 = __shfl_sync(0xffffffffu, eb, q * 4 + 1);
        const float e6 = __shfl_sync(0xffffffffu, eb, q * 4 + 2);
        const float e7 = __shfl_sync(0xffffffffu, eb, q * 4 + 3);
        #pragma unroll
        for (int i = 0; i < 8; ++i) {
            float a = fmaf(d0[i].x, e0, sve[i]);
            a = fmaf(d0[i].y, e1, a);
            a = fmaf(d0[i].z, e2, a);
            a = fmaf(d0[i].w, e3, a);
            a = fmaf(d1[i].x, e4, a);
            a = fmaf(d1[i].y, e5, a);
            a = fmaf(d1[i].z, e6, a);
            sve[i] = fmaf(d1[i].w, e7, a);
        }

        acc_tiles += 2;

        // ---- flush at batch boundary (rounds never straddle: T even) or end ----
        const bool flush = (rr + 1 == nrounds) || (((T + 2) & 127) == 0);
        if (flush) {
            // reduce sv/sve over the 8 q-lanes of each channel group
            float rv[8], rve[8];
            #pragma unroll
            for (int i = 0; i < 8; ++i) { rv[i] = sv[i]; rve[i] = sve[i]; }
            #pragma unroll
            for (int off = 4; off > 0; off >>= 1) {
                #pragma unroll
                for (int i = 0; i < 8; ++i) {
                    rv[i]  += __shfl_down_sync(0xffffffffu, rv[i],  off, 8);
                    rve[i] += __shfl_down_sync(0xffffffffu, rve[i], off, 8);
                }
            }
            if (q == 0) {
                #pragma unroll
                for (int i = 0; i < 8; ++i) {
                    atomicAdd(&g_sumc[b * C_ + cg * 8 + i], rv[i]);
                    atomicAdd(&g_num [b * C_ + cg * 8 + i], rve[i]);
                }
            }
            if (w == 0) {
                float e2s = run_e, m2s = run_m;
                #pragma unroll
                for (int off = 16; off > 0; off >>= 1) {
                    e2s += __shfl_down_sync(0xffffffffu, e2s, off);
                    m2s += __shfl_down_sync(0xffffffffu, m2s, off);
                }
                if (lane == 0) { atomicAdd(&g_D[b], e2s); atomicAdd(&g_summ[b], m2s); }
            }
            __threadfence();
            __syncthreads();
            if (t == 0) {
                unsigned n = (unsigned)acc_tiles;
                unsigned old = atomicAdd(&g_cnt[b], n);
                s_last = (old + n == (unsigned)TPB_TILES);
            }
            __syncthreads();
            if (s_last) {
                finalize_batch(b, sm, t, lane, w,
                               w_cm1, b_cm1, ln_w, ln_b, w_cm2, b_cm2,
                               w_net1, w_net2, w_fc, bn_w, bn_b, bn_mean, bn_var,
                               w_kfc, out);
            }
            // reset accumulators for the next batch segment
            #pragma unroll
            for (int i = 0; i < 8; ++i) { sv[i] = 0.f; sve[i] = 0.f; }
            run_e = 0.f; run_m = 0.f;
            acc_tiles = 0;
        }
    }
}

// ---------------- launch ----------------
extern "C" void kernel_launch(void* const* d_in, const int* in_sizes, int n_in,
                              void* d_out, int out_size) {
    const float* x      = (const float*)d_in[0];
    const float* w_mask = (const float*)d_in[1];
    const float* b_mask = (const float*)d_in[2];
    const float* w_cm1  = (const float*)d_in[3];
    const float* b_cm1  = (const float*)d_in[4];
    const float* ln_w   = (const float*)d_in[5];
    const float* ln_b   = (const float*)d_in[6];
    const float* w_cm2  = (const float*)d_in[7];
    const float* b_cm2  = (const float*)d_in[8];
    const float* w_net1 = (const float*)d_in[9];
    const float* w_net2 = (const float*)d_in[10];
    const float* w_fc   = (const float*)d_in[11];
    const float* bn_w   = (const float*)d_in[12];
    const float* bn_b   = (const float*)d_in[13];
    const float* bn_mean= (const float*)d_in[14];
    const float* bn_var = (const float*)d_in[15];
    const float* w_kfc  = (const float*)d_in[16];
    float* out = (float*)d_out;

    fused<<<GRID, 256>>>(x, w_mask, b_mask,
                          w_cm1, b_cm1, ln_w, ln_b, w_cm2, b_cm2,
                          w_net1, w_net2, w_fc, bn_w, bn_b, bn_mean, bn_var,
                          w_kfc, out);
}

// round 17
// speedup vs baseline: 1.9244x; 1.1659x over previous
#include <cuda_runtime.h>
#include <math.h>

// ---------------- problem constants ----------------
#define B_   64
#define C_   256
#define HW_  4096            // 64*64
#define GRID 304             // 2 CTAs/SM x 152 SMs -> exactly one full wave
#define TPB_TILES 128        // 32-pos tiles per batch
#define PLANES 128
#define HIDDEN 16
#define K_   8
#define ATT_CH 4
#define EPS_ 1e-5f

// ---------------- device scratch (zero-init at load; finalize re-zeros) ----------------
__device__ float    g_sumc[B_ * C_];
__device__ float    g_num [B_ * C_];
__device__ float    g_D   [B_];
__device__ float    g_summ[B_];
__device__ unsigned g_cnt [B_];     // tiles accumulated per batch

__device__ __forceinline__ void prefetch_l2(const void* p) {
    asm volatile("prefetch.global.L2 [%0];" :: "l"(p));
}

// ---------------- finalize: runs in whichever CTA completes a batch ----------------
__device__ __forceinline__ void finalize_batch(
        int b, float* sm, int t, int lane, int wp,
        const float* __restrict__ w_cm1, const float* __restrict__ b_cm1,
        const float* __restrict__ ln_w,  const float* __restrict__ ln_b,
        const float* __restrict__ w_cm2, const float* __restrict__ b_cm2,
        const float* __restrict__ w_net1, const float* __restrict__ w_net2,
        const float* __restrict__ w_fc,
        const float* __restrict__ bn_w,  const float* __restrict__ bn_b,
        const float* __restrict__ bn_mean, const float* __restrict__ bn_var,
        const float* __restrict__ w_kfc,
        float* __restrict__ out) {
    float* ctx   = sm;            // 256
    float* bcv   = sm + 256;      // 256
    float* tvs   = sm + 512;      // 128
    float* tg    = sm + 640;      // 128
    float* sout  = sm + 768;      // 256
    float* red_s = sm + 1024;     // 4
    float* red_q = sm + 1028;     // 4
    float* red_a = sm + 1032;     // 8
    float* hid   = sm + 1040;     // 16
    float* o8    = sm + 1056;     // 8
    float* kar   = sm + 1064;     // 4
    float* fvv   = sm + 1072;     // 8
    float* shm   = sm + 1080;     // 1

    const float Dv    = __ldcg(&g_D[b]);
    const float summv = __ldcg(&g_summ[b]);
    const float numv  = __ldcg(&g_num [b * C_ + t]);
    const float sumcv = __ldcg(&g_sumc[b * C_ + t]);

    ctx[t] = numv  * (1.f / Dv);
    bcv[t] = sumcv * (1.f / (float)HW_);
    {
        float s = sumcv * (1.f / (float)HW_);
        #pragma unroll
        for (int off = 16; off > 0; off >>= 1) s += __shfl_down_sync(0xffffffffu, s, off);
        if (lane == 0) red_a[wp] = s;
    }
    __syncthreads();   // RACE FIX: all threads loaded g_* before any re-zero

    // re-zero scratch for next graph replay
    g_num [b * C_ + t] = 0.f;
    g_sumc[b * C_ + t] = 0.f;
    if (t == 0) { g_D[b] = 0.f; g_summ[b] = 0.f; g_cnt[b] = 0u; shm[0] = summv * (1.f / (float)HW_); }
    __syncthreads();

    const float aval = (red_a[0] + red_a[1] + red_a[2] + red_a[3] +
                        red_a[4] + red_a[5] + red_a[6] + red_a[7]) * (1.f / (float)C_);
    const float mv = shm[0];

    // conv1 (128x256): warp wp -> planes wp*16..+15
    {
        const float4* ctx4 = reinterpret_cast<const float4*>(ctx);
        const float4 c0 = ctx4[lane];
        const float4 c1 = ctx4[lane + 32];
        #pragma unroll 4
        for (int i = 0; i < 16; ++i) {
            int p = wp * 16 + i;
            const float4* w4 = reinterpret_cast<const float4*>(w_cm1 + p * C_);
            float4 a0 = w4[lane];
            float4 a1 = w4[lane + 32];
            float pr = a0.x * c0.x + a0.y * c0.y + a0.z * c0.z + a0.w * c0.w
                     + a1.x * c1.x + a1.y * c1.y + a1.z * c1.z + a1.w * c1.w;
            #pragma unroll
            for (int off = 16; off > 0; off >>= 1)
                pr += __shfl_down_sync(0xffffffffu, pr, off);
            if (lane == 0) tvs[p] = pr + b_cm1[p];
        }
    }
    __syncthreads();

    // LayerNorm(128) + exact GELU
    {
        float tvv = (t < PLANES) ? tvs[t] : 0.f;
        float s1 = tvv, s2 = tvv * tvv;
        #pragma unroll
        for (int off = 16; off > 0; off >>= 1) {
            s1 += __shfl_down_sync(0xffffffffu, s1, off);
            s2 += __shfl_down_sync(0xffffffffu, s2, off);
        }
        if (t < PLANES && lane == 0) { red_s[wp] = s1; red_q[wp] = s2; }
        __syncthreads();
        if (t < PLANES) {
            float S  = red_s[0] + red_s[1] + red_s[2] + red_s[3];
            float SQ = red_q[0] + red_q[1] + red_q[2] + red_q[3];
            float mu  = S * (1.f / PLANES);
            float var = SQ * (1.f / PLANES) - mu * mu;
            float tn = (tvv - mu) * rsqrtf(var + EPS_) * ln_w[t] + ln_b[t];
            tg[t] = 0.5f * tn * (1.f + erff(tn * 0.70710678118654752f));
        }
    }
    __syncthreads();

    // conv2 (256x128): warp wp -> channels wp*32..+31
    {
        const float4* tg4 = reinterpret_cast<const float4*>(tg);
        const float4 g0 = tg4[lane];
        #pragma unroll 4
        for (int i = 0; i < 32; ++i) {
            int ch = wp * 32 + i;
            const float4* w4 = reinterpret_cast<const float4*>(w_cm2 + ch * PLANES);
            float4 a0 = w4[lane];
            float pr = a0.x * g0.x + a0.y * g0.y + a0.z * g0.z + a0.w * g0.w;
            #pragma unroll
            for (int off = 16; off > 0; off >>= 1)
                pr += __shfl_down_sync(0xffffffffu, pr, off);
            if (lane == 0)
                sout[ch] = bcv[ch] + pr + b_cm2[ch] + ((ch & 1) ? mv : aval);
        }
    }
    __syncthreads();

    // net1 (16x256): warp wp -> hidden wp*2, wp*2+1
    {
        const float4* so4 = reinterpret_cast<const float4*>(sout);
        const float4 s0 = so4[lane];
        const float4 s1v = so4[lane + 32];
        #pragma unroll
        for (int jj = 0; jj < 2; ++jj) {
            int hh = wp * 2 + jj;
            const float4* w4 = reinterpret_cast<const float4*>(w_net1 + hh * C_);
            float4 a0 = w4[lane];
            float4 a1 = w4[lane + 32];
            float pr = a0.x * s0.x + a0.y * s0.y + a0.z * s0.z + a0.w * s0.w
                     + a1.x * s1v.x + a1.y * s1v.y + a1.z * s1v.z + a1.w * s1v.w;
            #pragma unroll
            for (int off = 16; off > 0; off >>= 1)
                pr += __shfl_down_sync(0xffffffffu, pr, off);
            if (lane == 0) hid[hh] = fmaxf(pr, 0.f);
        }
    }
    __syncthreads();

    if (t < K_) {
        float o = 0.f;
        #pragma unroll
        for (int q2 = 0; q2 < HIDDEN; ++q2) o = fmaf(hid[q2], w_net2[t * HIDDEN + q2], o);
        o8[t] = o;
    }
    __syncthreads();
    if (t < ATT_CH) {
        float ka = 0.f;
        #pragma unroll
        for (int k = 0; k < K_; ++k) ka = fmaf(o8[k], w_fc[t * K_ + k], ka);
        ka = (ka - bn_mean[t]) * rsqrtf(bn_var[t] + EPS_) * bn_w[t] + bn_b[t];
        kar[t] = fmaxf(ka, 0.f);
    }
    __syncthreads();
    if (t < K_) {
        float kk = 0.f;
        #pragma unroll
        for (int q2 = 0; q2 < ATT_CH; ++q2) kk = fmaf(kar[q2], w_kfc[t * ATT_CH + q2], kk);
        float ker = 1.f / (1.f + __expf(-kk));
        fvv[t] = o8[t] * ker * (1.f / 30.f);
    }
    __syncthreads();
    if (t == 0) {
        float mx = -1e30f;
        #pragma unroll
        for (int k = 0; k < K_; ++k) mx = fmaxf(mx, fvv[k]);
        float e[K_], s = 0.f;
        #pragma unroll
        for (int k = 0; k < K_; ++k) { e[k] = __expf(fvv[k] - mx); s += e[k]; }
        float inv = 1.f / s;
        #pragma unroll
        for (int k = 0; k < K_; ++k) out[b * K_ + k] = e[k] * inv;
    }
    __syncthreads();   // smem handed back to the streaming loop
}

// ---------------- persistent fused kernel ----------------
__global__ __launch_bounds__(256, 2) void fused(
        const float* __restrict__ x,
        const float* __restrict__ w_mask, const float* __restrict__ b_mask,
        const float* __restrict__ w_cm1, const float* __restrict__ b_cm1,
        const float* __restrict__ ln_w,  const float* __restrict__ ln_b,
        const float* __restrict__ w_cm2, const float* __restrict__ b_cm2,
        const float* __restrict__ w_net1, const float* __restrict__ w_net2,
        const float* __restrict__ w_fc,
        const float* __restrict__ bn_w,  const float* __restrict__ bn_b,
        const float* __restrict__ bn_mean, const float* __restrict__ bn_var,
        const float* __restrict__ w_kfc,
        float* __restrict__ out) {
    // smem: double-buffered partials AL[2][8][64], AM[2][8][64]; finalize aliases [0..1081)
    __shared__ __align__(16) float sm[2064];
    __shared__ int s_last;
    float* AL = sm;           // slot s at sm + s*512
    float* AM = sm + 1024;    // slot s at sm + 1024 + s*512

    const int t    = threadIdx.x;    // 0..255
    const int lane = t & 31;
    const int w    = t >> 5;
    const int r    = blockIdx.x;

    // even tile ranges: 144 CTAs x 28 + 160 CTAs x 26 = 8192 tiles
    const int nrounds = (r < 144) ? 14 : 13;                  // rounds of 2 tiles
    const int tstart  = (r < 144) ? r * 28 : 4032 + (r - 144) * 26;

    const int cg = t >> 3;           // channel group 0..31 (channels cg*8+i)
    const int q  = t & 7;            // position quad 0..7

    // hoisted mask weights for this thread's 8 channels
    float4 wv0 = *reinterpret_cast<const float4*>(w_mask + cg * 8);
    float4 wv1 = *reinterpret_cast<const float4*>(w_mask + cg * 8 + 4);
    const float wreg[8] = {wv0.x, wv0.y, wv0.z, wv0.w, wv1.x, wv1.y, wv1.z, wv1.w};
    const float bm = b_mask[0];

    const float4* x4 = reinterpret_cast<const float4*>(x);
    const size_t croff = (size_t)(cg * 8) * (HW_ / 4) + q;   // channel-row + quad offset

    // per-thread accumulators (reset at each flush)
    float sv[8], sve[8];
    #pragma unroll
    for (int i = 0; i < 8; ++i) { sv[i] = 0.f; sve[i] = 0.f; }
    float run_e = 0.f, run_m = 0.f;     // warp 0 lanes
    int acc_tiles = 0;

    #pragma unroll 1
    for (int rr = 0; rr < nrounds; ++rr) {
        const int T = tstart + 2 * rr;       // global tile index (even)
        const int b = T >> 7;
        const size_t base = (size_t)b * C_ * (HW_ / 4) + croff
                          + (size_t)(T & 127) * 8;
        const int slot = rr & 1;

        // ---- 16 independent coalesced streaming LDG.128 (2KB/warp burst) ----
        float4 d0[8], d1[8];
        #pragma unroll
        for (int i = 0; i < 8; ++i) {
            d0[i] = __ldcs(x4 + base + (size_t)i * (HW_ / 4));
            d1[i] = __ldcs(x4 + base + (size_t)i * (HW_ / 4) + 8);
        }

        // ---- L2 prefetch of NEXT round's lines (no registers, no dependency):
        //      keeps DRAM busy through the compute/barrier phases below.
        if (rr + 1 < nrounds) {
            const int Tn = T + 2;
            const size_t nbase = (size_t)(Tn >> 7) * C_ * (HW_ / 4) + croff
                               + (size_t)(Tn & 127) * 8;
            #pragma unroll
            for (int i = 0; i < 8; ++i) {
                prefetch_l2(x4 + nbase + (size_t)i * (HW_ / 4));
                prefetch_l2(x4 + nbase + (size_t)i * (HW_ / 4) + 8);
            }
        }

        // ---- phase2: logit / max / channel-sum partials for both tiles ----
        float4 lp0 = make_float4(0.f, 0.f, 0.f, 0.f);
        float4 lp1 = make_float4(0.f, 0.f, 0.f, 0.f);
        float4 mp0 = make_float4(-1e30f, -1e30f, -1e30f, -1e30f);
        float4 mp1 = make_float4(-1e30f, -1e30f, -1e30f, -1e30f);
        #pragma unroll
        for (int i = 0; i < 8; ++i) {
            const float wc = wreg[i];
            lp0.x = fmaf(d0[i].x, wc, lp0.x); lp0.y = fmaf(d0[i].y, wc, lp0.y);
            lp0.z = fmaf(d0[i].z, wc, lp0.z); lp0.w = fmaf(d0[i].w, wc, lp0.w);
            lp1.x = fmaf(d1[i].x, wc, lp1.x); lp1.y = fmaf(d1[i].y, wc, lp1.y);
            lp1.z = fmaf(d1[i].z, wc, lp1.z); lp1.w = fmaf(d1[i].w, wc, lp1.w);
            mp0.x = fmaxf(mp0.x, d0[i].x);    mp0.y = fmaxf(mp0.y, d0[i].y);
            mp0.z = fmaxf(mp0.z, d0[i].z);    mp0.w = fmaxf(mp0.w, d0[i].w);
            mp1.x = fmaxf(mp1.x, d1[i].x);    mp1.y = fmaxf(mp1.y, d1[i].y);
            mp1.z = fmaxf(mp1.z, d1[i].z);    mp1.w = fmaxf(mp1.w, d1[i].w);
            sv[i] += (d0[i].x + d0[i].y) + (d0[i].z + d0[i].w)
                   + (d1[i].x + d1[i].y) + (d1[i].z + d1[i].w);
        }
        // intra-warp reduce over the 4 channel-groups (lanes stride 8, same q)
        #pragma unroll
        for (int off = 8; off <= 16; off <<= 1) {
            lp0.x += __shfl_down_sync(0xffffffffu, lp0.x, off);
            lp0.y += __shfl_down_sync(0xffffffffu, lp0.y, off);
            lp0.z += __shfl_down_sync(0xffffffffu, lp0.z, off);
            lp0.w += __shfl_down_sync(0xffffffffu, lp0.w, off);
            lp1.x += __shfl_down_sync(0xffffffffu, lp1.x, off);
            lp1.y += __shfl_down_sync(0xffffffffu, lp1.y, off);
            lp1.z += __shfl_down_sync(0xffffffffu, lp1.z, off);
            lp1.w += __shfl_down_sync(0xffffffffu, lp1.w, off);
            mp0.x = fmaxf(mp0.x, __shfl_down_sync(0xffffffffu, mp0.x, off));
            mp0.y = fmaxf(mp0.y, __shfl_down_sync(0xffffffffu, mp0.y, off));
            mp0.z = fmaxf(mp0.z, __shfl_down_sync(0xffffffffu, mp0.z, off));
            mp0.w = fmaxf(mp0.w, __shfl_down_sync(0xffffffffu, mp0.w, off));
            mp1.x = fmaxf(mp1.x, __shfl_down_sync(0xffffffffu, mp1.x, off));
            mp1.y = fmaxf(mp1.y, __shfl_down_sync(0xffffffffu, mp1.y, off));
            mp1.z = fmaxf(mp1.z, __shfl_down_sync(0xffffffffu, mp1.z, off));
            mp1.w = fmaxf(mp1.w, __shfl_down_sync(0xffffffffu, mp1.w, off));
        }
        // store to this round's slot; WAR vs combine(rr-2) separated by barrier(rr-1)
        if (lane < 8) {
            *reinterpret_cast<float4*>(AL + slot * 512 + w * 64 + lane * 4)      = lp0;
            *reinterpret_cast<float4*>(AL + slot * 512 + w * 64 + 32 + lane * 4) = lp1;
            *reinterpret_cast<float4*>(AM + slot * 512 + w * 64 + lane * 4)      = mp0;
            *reinterpret_cast<float4*>(AM + slot * 512 + w * 64 + 32 + lane * 4) = mp1;
        }
        __syncthreads();     // the ONLY barrier per round

        // ---- combine (every warp redundantly; lane covers positions lane & lane+32)
        float la = bm, lb = bm;
        #pragma unroll
        for (int p = 0; p < 8; ++p) {
            la += AL[slot * 512 + p * 64 + lane];
            lb += AL[slot * 512 + p * 64 + 32 + lane];
        }
        const float ea = __expf(la);     // unnormalized softmax weights (logits O(3))
        const float eb = __expf(lb);
        if (w == 0) {
            run_e += ea + eb;
            float ma = -1e30f, mb2 = -1e30f;
            #pragma unroll
            for (int p = 0; p < 8; ++p) {
                ma  = fmaxf(ma,  AM[slot * 512 + p * 64 + lane]);
                mb2 = fmaxf(mb2, AM[slot * 512 + p * 64 + 32 + lane]);
            }
            run_m += ma + mb2;
        }

        // ---- phase3: weighted accumulate from the SAME registers ----
        const float e0 = __shfl_sync(0xffffffffu, ea, q * 4 + 0);
        const float e1 = __shfl_sync(0xffffffffu, ea, q * 4 + 1);
        const float e2 = __shfl_sync(0xffffffffu, ea, q * 4 + 2);
        const float e3 = __shfl_sync(0xffffffffu, ea, q * 4 + 3);
        const float e4 = __shfl_sync(0xffffffffu, eb, q * 4 + 0);
        const float e5 = __shfl_sync(0xffffffffu, eb, q * 4 + 1);
        const float e6 = __shfl_sync(0xffffffffu, eb, q * 4 + 2);
        const float e7 = __shfl_sync(0xffffffffu, eb, q * 4 + 3);
        #pragma unroll
        for (int i = 0; i < 8; ++i) {
            float a = fmaf(d0[i].x, e0, sve[i]);
            a = fmaf(d0[i].y, e1, a);
            a = fmaf(d0[i].z, e2, a);
            a = fmaf(d0[i].w, e3, a);
            a = fmaf(d1[i].x, e4, a);
            a = fmaf(d1[i].y, e5, a);
            a = fmaf(d1[i].z, e6, a);
            sve[i] = fmaf(d1[i].w, e7, a);
        }

        acc_tiles += 2;

        // ---- flush at batch boundary (rounds never straddle: T even) or end ----
        const bool flush = (rr + 1 == nrounds) || (((T + 2) & 127) == 0);
        if (flush) {
            float rv[8], rve[8];
            #pragma unroll
            for (int i = 0; i < 8; ++i) { rv[i] = sv[i]; rve[i] = sve[i]; }
            #pragma unroll
            for (int off = 4; off > 0; off >>= 1) {
                #pragma unroll
                for (int i = 0; i < 8; ++i) {
                    rv[i]  += __shfl_down_sync(0xffffffffu, rv[i],  off, 8);
                    rve[i] += __shfl_down_sync(0xffffffffu, rve[i], off, 8);
                }
            }
            if (q == 0) {
                #pragma unroll
                for (int i = 0; i < 8; ++i) {
                    atomicAdd(&g_sumc[b * C_ + cg * 8 + i], rv[i]);
                    atomicAdd(&g_num [b * C_ + cg * 8 + i], rve[i]);
                }
            }
            if (w == 0) {
                float e2s = run_e, m2s = run_m;
                #pragma unroll
                for (int off = 16; off > 0; off >>= 1) {
                    e2s += __shfl_down_sync(0xffffffffu, e2s, off);
                    m2s += __shfl_down_sync(0xffffffffu, m2s, off);
                }
                if (lane == 0) { atomicAdd(&g_D[b], e2s); atomicAdd(&g_summ[b], m2s); }
            }
            __threadfence();
            __syncthreads();
            if (t == 0) {
                unsigned n = (unsigned)acc_tiles;
                unsigned old = atomicAdd(&g_cnt[b], n);
                s_last = (old + n == (unsigned)TPB_TILES);
            }
            __syncthreads();
            if (s_last) {
                finalize_batch(b, sm, t, lane, w,
                               w_cm1, b_cm1, ln_w, ln_b, w_cm2, b_cm2,
                               w_net1, w_net2, w_fc, bn_w, bn_b, bn_mean, bn_var,
                               w_kfc, out);
            }
            #pragma unroll
            for (int i = 0; i < 8; ++i) { sv[i] = 0.f; sve[i] = 0.f; }
            run_e = 0.f; run_m = 0.f;
            acc_tiles = 0;
        }
    }
}

// ---------------- launch ----------------
extern "C" void kernel_launch(void* const* d_in, const int* in_sizes, int n_in,
                              void* d_out, int out_size) {
    const float* x      = (const float*)d_in[0];
    const float* w_mask = (const float*)d_in[1];
    const float* b_mask = (const float*)d_in[2];
    const float* w_cm1  = (const float*)d_in[3];
    const float* b_cm1  = (const float*)d_in[4];
    const float* ln_w   = (const float*)d_in[5];
    const float* ln_b   = (const float*)d_in[6];
    const float* w_cm2  = (const float*)d_in[7];
    const float* b_cm2  = (const float*)d_in[8];
    const float* w_net1 = (const float*)d_in[9];
    const float* w_net2 = (const float*)d_in[10];
    const float* w_fc   = (const float*)d_in[11];
    const float* bn_w   = (const float*)d_in[12];
    const float* bn_b   = (const float*)d_in[13];
    const float* bn_mean= (const float*)d_in[14];
    const float* bn_var = (const float*)d_in[15];
    const float* w_kfc  = (const float*)d_in[16];
    float* out = (float*)d_out;

    fused<<<GRID, 256>>>(x, w_mask, b_mask,
                          w_cm1, b_cm1, ln_w, ln_b, w_cm2, b_cm2,
                          w_net1, w_net2, w_fc, bn_w, bn_b, bn_mean, bn_var,
                          w_kfc, out);
}